// round 1
// baseline (speedup 1.0000x reference)
#include <cuda_runtime.h>
#include <math.h>

// ---------------- problem constants ----------------
#define Bc 2
#define Sc 2048
#define Dc 1024
#define Hc 16
#define DHc 64
#define Fc 4096
#define Ec 8
#define NTOK (Bc * Sc)          // 4096 tokens
#define LN_EPS 1e-6f

// ---------------- scratch layout (static device memory; no allocs) ----------
// q,k,v,ctx,attn,inter,moe : 7 * 4096*1024          = 29,360,128
// h (MoE hidden)           : 4096*4096              = 16,777,216
// scores                   : 2*16*2048*2048         = 134,217,728
// gate                     : 4096*8                 = 32,768
// total                                             = 180,387,840 floats (~722 MB)
static const size_t SZ_MAT   = (size_t)NTOK * Dc;        // 4,194,304
static const size_t OFF_Q    = 0;
static const size_t OFF_K    = 1 * SZ_MAT;
static const size_t OFF_V    = 2 * SZ_MAT;
static const size_t OFF_CTX  = 3 * SZ_MAT;
static const size_t OFF_ATTN = 4 * SZ_MAT;
static const size_t OFF_INT  = 5 * SZ_MAT;
static const size_t OFF_MOE  = 6 * SZ_MAT;
static const size_t OFF_H    = 7 * SZ_MAT;                           // len 16,777,216
static const size_t OFF_SC   = OFF_H + (size_t)NTOK * Fc;            // len 134,217,728
static const size_t OFF_GATE = OFF_SC + (size_t)Bc * Hc * Sc * Sc;   // len 32,768
static const size_t SCRATCH_TOTAL = OFF_GATE + (size_t)NTOK * Ec;

__device__ float g_scratch[SCRATCH_TOTAL];

// ---------------- helpers ----------------
__device__ __forceinline__ float gelu_tanh(float x) {
    // JAX default: approximate=True (tanh form)
    float x3 = x * x * x;
    float t  = tanhf(0.7978845608028654f * (x + 0.044715f * x3));
    return 0.5f * x * (1.0f + t);
}

// ---------------- generic tiled SGEMM -------------------------------------
// C[M,N] = A[M,K] * op(B) with per-launch epilogue.
// TRANSB=false: B is [K,N] row-major (ldb). TRANSB=true: B is [N,K] row-major.
// EPI: 0 = (+bias?) store
//      1 = gelu(acc + bias)
//      2 = C  = aux[m*aux_stride] * (acc + bias)       (gate-weighted write)
//      5 = C += aux[m*aux_stride] * (acc + bias)       (gate-weighted accumulate)
//      3 = C  = acc*alpha + aux[m*ldaux + n]           (scores: scale + mask)
// Batched over blockIdx.z with z = b*Hdim + h; pointer offsets per (b,h).
#define BM 128
#define BN 128
#define BK 16
#define TM 8
#define TN 8

template <bool TRANSB, int EPI>
__global__ __launch_bounds__(256)
void gemm_kernel(const float* __restrict__ A, const float* __restrict__ B,
                 float* __restrict__ C,
                 const float* __restrict__ bias, const float* __restrict__ aux,
                 int M, int N, int K, int lda, int ldb, int ldc,
                 int aux_stride, int ldaux, float alpha, int Hdim,
                 long long aOB, long long aOH, long long bOB, long long bOH,
                 long long cOB, long long cOH, long long xOB)
{
    __shared__ float As[BK][BM + 4];
    __shared__ float Bs[BK][BN + 4];

    const int tid = threadIdx.x;
    const int tx  = tid & 15;   // 0..15 -> N direction
    const int ty  = tid >> 4;   // 0..15 -> M direction
    const int m0  = blockIdx.y * BM;
    const int n0  = blockIdx.x * BN;

    const int z  = blockIdx.z;
    const int bb = z / Hdim;
    const int hh = z - bb * Hdim;
    A += (size_t)bb * aOB + (size_t)hh * aOH;
    B += (size_t)bb * bOB + (size_t)hh * bOH;
    C += (size_t)bb * cOB + (size_t)hh * cOH;
    if (EPI == 3 || EPI == 2 || EPI == 5) aux += (size_t)bb * xOB;

    float acc[TM][TN];
#pragma unroll
    for (int i = 0; i < TM; i++)
#pragma unroll
        for (int j = 0; j < TN; j++) acc[i][j] = 0.0f;

    for (int k0 = 0; k0 < K; k0 += BK) {
        // ---- load A tile: 128 rows x 16 cols (K multiple of 16, M multiple of 128)
#pragma unroll
        for (int it = 0; it < 2; it++) {
            int lin = tid + it * 256;       // 0..511
            int row = lin >> 2;             // 0..127
            int c4  = lin & 3;              // 0..3
            const float4 va = *(const float4*)(A + (size_t)(m0 + row) * lda + k0 + c4 * 4);
            As[c4 * 4 + 0][row] = va.x;
            As[c4 * 4 + 1][row] = va.y;
            As[c4 * 4 + 2][row] = va.z;
            As[c4 * 4 + 3][row] = va.w;
        }
        // ---- load B tile
        if (TRANSB) {
            // B is [N,K]; tile = 128 n-rows x 16 k-cols (N multiple of 128 in NT uses)
#pragma unroll
            for (int it = 0; it < 2; it++) {
                int lin = tid + it * 256;
                int row = lin >> 2;
                int c4  = lin & 3;
                const float4 vb = *(const float4*)(B + (size_t)(n0 + row) * ldb + k0 + c4 * 4);
                Bs[c4 * 4 + 0][row] = vb.x;
                Bs[c4 * 4 + 1][row] = vb.y;
                Bs[c4 * 4 + 2][row] = vb.z;
                Bs[c4 * 4 + 3][row] = vb.w;
            }
        } else {
            // B is [K,N]; tile = 16 k-rows x 128 n-cols; N may be < 128 (ctx gemm)
#pragma unroll
            for (int it = 0; it < 2; it++) {
                int lin = tid + it * 256;
                int row = lin >> 5;          // 0..15
                int c4  = lin & 31;          // 0..31
                int col = n0 + c4 * 4;
                float4 vb = make_float4(0.f, 0.f, 0.f, 0.f);
                if (col < N)
                    vb = *(const float4*)(B + (size_t)(k0 + row) * ldb + col);
                *(float4*)&Bs[row][c4 * 4] = vb;
            }
        }
        __syncthreads();

#pragma unroll
        for (int kk = 0; kk < BK; kk++) {
            float ra[TM], rb[TN];
#pragma unroll
            for (int i = 0; i < TM; i++) ra[i] = As[kk][ty * TM + i];
#pragma unroll
            for (int j = 0; j < TN; j++) rb[j] = Bs[kk][tx * TN + j];
#pragma unroll
            for (int i = 0; i < TM; i++)
#pragma unroll
                for (int j = 0; j < TN; j++)
                    acc[i][j] = fmaf(ra[i], rb[j], acc[i][j]);
        }
        __syncthreads();
    }

    // ---- epilogue
#pragma unroll
    for (int i = 0; i < TM; i++) {
        const int m = m0 + ty * TM + i;
        float g = 0.0f;
        if (EPI == 2 || EPI == 5) g = aux[(size_t)m * aux_stride];
#pragma unroll
        for (int j = 0; j < TN; j++) {
            const int n = n0 + tx * TN + j;
            if (n < N) {
                float val = acc[i][j];
                const size_t cidx = (size_t)m * ldc + n;
                if (EPI == 0) {
                    if (bias) val += bias[n];
                    C[cidx] = val;
                } else if (EPI == 1) {
                    C[cidx] = gelu_tanh(val + bias[n]);
                } else if (EPI == 2) {
                    C[cidx] = g * (val + bias[n]);
                } else if (EPI == 5) {
                    C[cidx] += g * (val + bias[n]);
                } else if (EPI == 3) {
                    C[cidx] = val * alpha + aux[(size_t)m * ldaux + n];
                }
            }
        }
    }
}

// ---------------- softmax over rows of length 2048 -------------------------
__global__ void softmax2048(float* __restrict__ data)
{
    __shared__ float red[256];
    const size_t base = (size_t)blockIdx.x * 2048;
    const int tid = threadIdx.x;

    float v[8];
    float mx = -INFINITY;
#pragma unroll
    for (int i = 0; i < 8; i++) {
        v[i] = data[base + tid + i * 256];
        mx = fmaxf(mx, v[i]);
    }
    red[tid] = mx; __syncthreads();
    for (int s = 128; s > 0; s >>= 1) {
        if (tid < s) red[tid] = fmaxf(red[tid], red[tid + s]);
        __syncthreads();
    }
    mx = red[0]; __syncthreads();

    float sum = 0.f;
#pragma unroll
    for (int i = 0; i < 8; i++) { v[i] = expf(v[i] - mx); sum += v[i]; }
    red[tid] = sum; __syncthreads();
    for (int s = 128; s > 0; s >>= 1) {
        if (tid < s) red[tid] += red[tid + s];
        __syncthreads();
    }
    const float inv = 1.0f / red[0];
#pragma unroll
    for (int i = 0; i < 8; i++) data[base + tid + i * 256] = v[i] * inv;
}

// ---------------- LayerNorm(x + r) over rows of length 1024 ----------------
__global__ void ln_residual(const float* __restrict__ x, const float* __restrict__ r,
                            const float* __restrict__ g, const float* __restrict__ b,
                            float* __restrict__ out)
{
    __shared__ float red[256];
    const size_t base = (size_t)blockIdx.x * Dc;
    const int tid = threadIdx.x;

    float v[4];
    float s = 0.f;
#pragma unroll
    for (int i = 0; i < 4; i++) {
        const int c = tid + i * 256;
        v[i] = x[base + c] + r[base + c];
        s += v[i];
    }
    red[tid] = s; __syncthreads();
    for (int st = 128; st > 0; st >>= 1) {
        if (tid < st) red[tid] += red[tid + st];
        __syncthreads();
    }
    const float mean = red[0] * (1.0f / Dc);
    __syncthreads();

    float ss = 0.f;
#pragma unroll
    for (int i = 0; i < 4; i++) {
        const float d = v[i] - mean;
        ss += d * d;
    }
    red[tid] = ss; __syncthreads();
    for (int st = 128; st > 0; st >>= 1) {
        if (tid < st) red[tid] += red[tid + st];
        __syncthreads();
    }
    const float rstd = rsqrtf(red[0] * (1.0f / Dc) + LN_EPS);
#pragma unroll
    for (int i = 0; i < 4; i++) {
        const int c = tid + i * 256;
        out[base + c] = (v[i] - mean) * rstd * g[c] + b[c];
    }
}

// ---------------- gate: softmax(x @ gate_w + gate_b) over E=8 --------------
__global__ void gate_kernel(const float* __restrict__ x, const float* __restrict__ gw,
                            const float* __restrict__ gb,
                            float* __restrict__ gate, float* __restrict__ gate_out)
{
    const int m   = blockIdx.x;
    const int tid = threadIdx.x;
    const int wid = tid >> 5;   // expert id (8 warps)
    const int lane = tid & 31;
    __shared__ float logits[Ec];

    float s = 0.f;
    const float* xr = x + (size_t)m * Dc;
    for (int d = lane; d < Dc; d += 32) s += xr[d] * gw[d * Ec + wid];
#pragma unroll
    for (int o = 16; o > 0; o >>= 1) s += __shfl_down_sync(0xffffffffu, s, o);
    if (lane == 0) logits[wid] = s + gb[wid];
    __syncthreads();

    if (tid == 0) {
        float mx = logits[0];
#pragma unroll
        for (int e = 1; e < Ec; e++) mx = fmaxf(mx, logits[e]);
        float p[Ec]; float sum = 0.f;
#pragma unroll
        for (int e = 0; e < Ec; e++) { p[e] = expf(logits[e] - mx); sum += p[e]; }
        const float inv = 1.0f / sum;
#pragma unroll
        for (int e = 0; e < Ec; e++) {
            const float pv = p[e] * inv;
            gate[(size_t)m * Ec + e] = pv;
            if (gate_out) gate_out[(size_t)m * Ec + e] = pv;
        }
    }
}

// ---------------- launch ----------------------------------------------------
extern "C" void kernel_launch(void* const* d_in, const int* in_sizes, int n_in,
                              void* d_out, int out_size)
{
    const float* hidden = (const float*)d_in[0];
    const float* mask   = (const float*)d_in[1];
    const float* wq = (const float*)d_in[2];  const float* bq = (const float*)d_in[3];
    const float* wk = (const float*)d_in[4];  const float* bk = (const float*)d_in[5];
    const float* wv = (const float*)d_in[6];  const float* bv = (const float*)d_in[7];
    const float* wo = (const float*)d_in[8];  const float* bo = (const float*)d_in[9];
    const float* ln1_g = (const float*)d_in[10]; const float* ln1_b = (const float*)d_in[11];
    const float* gate_w = (const float*)d_in[12]; const float* gate_b = (const float*)d_in[13];
    const float* w1 = (const float*)d_in[14]; const float* b1 = (const float*)d_in[15];
    const float* w2 = (const float*)d_in[16]; const float* b2 = (const float*)d_in[17];
    const float* ln2_g = (const float*)d_in[18]; const float* ln2_b = (const float*)d_in[19];

    float* base = nullptr;
    cudaGetSymbolAddress((void**)&base, g_scratch);
    float* q      = base + OFF_Q;
    float* k      = base + OFF_K;
    float* v      = base + OFF_V;
    float* ctx    = base + OFF_CTX;
    float* attn   = base + OFF_ATTN;
    float* inter  = base + OFF_INT;
    float* moe    = base + OFF_MOE;
    float* hbuf   = base + OFF_H;
    float* scores = base + OFF_SC;
    float* gate   = base + OFF_GATE;

    float* out = (float*)d_out;
    float* gate_out = nullptr;
    if ((size_t)out_size >= (size_t)NTOK * Dc + (size_t)NTOK * Ec)
        gate_out = out + (size_t)NTOK * Dc;

    const dim3 blk(256);

    // 1) Q, K, V projections: [4096,1024] @ [1024,1024] + bias
    {
        dim3 grid(Dc / BN, NTOK / BM, 1);
        gemm_kernel<false, 0><<<grid, blk>>>(hidden, wq, q, bq, nullptr,
            NTOK, Dc, Dc, Dc, Dc, Dc, 0, 0, 0.f, 1, 0, 0, 0, 0, 0, 0, 0);
        gemm_kernel<false, 0><<<grid, blk>>>(hidden, wk, k, bk, nullptr,
            NTOK, Dc, Dc, Dc, Dc, Dc, 0, 0, 0.f, 1, 0, 0, 0, 0, 0, 0, 0);
        gemm_kernel<false, 0><<<grid, blk>>>(hidden, wv, v, bv, nullptr,
            NTOK, Dc, Dc, Dc, Dc, Dc, 0, 0, 0.f, 1, 0, 0, 0, 0, 0, 0, 0);
    }

    // 2) scores[b,h] = (Q_bh @ K_bh^T) / 8 + mask[b]
    {
        dim3 grid(Sc / BN, Sc / BM, Bc * Hc);
        gemm_kernel<true, 3><<<grid, blk>>>(q, k, scores, nullptr, mask,
            Sc, Sc, DHc, Dc, Dc, Sc,
            0, Sc, 0.125f, Hc,
            (long long)Sc * Dc, DHc,
            (long long)Sc * Dc, DHc,
            (long long)Hc * Sc * Sc, (long long)Sc * Sc,
            (long long)Sc * Sc);
    }

    // 3) row softmax over last dim (length 2048)
    softmax2048<<<Bc * Hc * Sc, 256>>>(scores);

    // 4) ctx[b,h] = probs_bh @ V_bh  (N = 64)
    {
        dim3 grid(1, Sc / BM, Bc * Hc);
        gemm_kernel<false, 0><<<grid, blk>>>(scores, v, ctx, nullptr, nullptr,
            Sc, DHc, Sc, Sc, Dc, Dc,
            0, 0, 0.f, Hc,
            (long long)Hc * Sc * Sc, (long long)Sc * Sc,
            (long long)Sc * Dc, DHc,
            (long long)Sc * Dc, DHc, 0);
    }

    // 5) output projection
    {
        dim3 grid(Dc / BN, NTOK / BM, 1);
        gemm_kernel<false, 0><<<grid, blk>>>(ctx, wo, attn, bo, nullptr,
            NTOK, Dc, Dc, Dc, Dc, Dc, 0, 0, 0.f, 1, 0, 0, 0, 0, 0, 0, 0);
    }

    // 6) inter = LN1(attn + hidden)
    ln_residual<<<NTOK, 256>>>(attn, hidden, ln1_g, ln1_b, inter);

    // 7) gate probs (also written straight to output region)
    gate_kernel<<<NTOK, 256>>>(inter, gate_w, gate_b, gate, gate_out);

    // 8) MoE: for each expert, h = gelu(inter @ w1_e + b1_e); moe (+)= gate_e * (h @ w2_e + b2_e)
    for (int e = 0; e < Ec; e++) {
        dim3 gh(Fc / BN, NTOK / BM, 1);
        gemm_kernel<false, 1><<<gh, blk>>>(inter, w1 + (size_t)e * Dc * Fc, hbuf,
            b1 + (size_t)e * Fc, nullptr,
            NTOK, Fc, Dc, Dc, Fc, Fc, 0, 0, 0.f, 1, 0, 0, 0, 0, 0, 0, 0);

        dim3 gy(Dc / BN, NTOK / BM, 1);
        if (e == 0) {
            gemm_kernel<false, 2><<<gy, blk>>>(hbuf, w2 + (size_t)e * Fc * Dc, moe,
                b2 + (size_t)e * Dc, gate + e,
                NTOK, Dc, Fc, Fc, Dc, Dc, Ec, 0, 0.f, 1, 0, 0, 0, 0, 0, 0, 0);
        } else {
            gemm_kernel<false, 5><<<gy, blk>>>(hbuf, w2 + (size_t)e * Fc * Dc, moe,
                b2 + (size_t)e * Dc, gate + e,
                NTOK, Dc, Fc, Fc, Dc, Dc, Ec, 0, 0.f, 1, 0, 0, 0, 0, 0, 0, 0);
        }
    }

    // 9) output = LN2(moe + inter)
    ln_residual<<<NTOK, 256>>>(moe, inter, ln2_g, ln2_b, out);
}

// round 3
// speedup vs baseline: 5.4713x; 5.4713x over previous
#include <cuda_runtime.h>
#include <cuda_fp16.h>
#include <math.h>
#include <stdint.h>

// ---------------- problem constants ----------------
#define Bc 2
#define Sc 2048
#define Dc 1024
#define Hc 16
#define DHc 64
#define Fc 4096
#define Ec 8
#define NTOK (Bc * Sc)
#define LN_EPS 1e-6f

// ---------------- fp32 scratch ----------------
static const size_t F_SC    = 0;                                   // scores  B*H*S*S
static const size_t F_ATTN  = F_SC  + (size_t)Bc * Hc * Sc * Sc;
static const size_t F_INT   = F_ATTN + (size_t)NTOK * Dc;
static const size_t F_MOE   = F_INT  + (size_t)NTOK * Dc;
static const size_t F_GATE  = F_MOE  + (size_t)NTOK * Dc;
static const size_t F_TOTAL = F_GATE + (size_t)NTOK * Ec;
__device__ float g_f32[F_TOTAL];

// ---------------- fp16 scratch ----------------
static const size_t H_HID  = 0;
static const size_t H_Q    = H_HID + (size_t)NTOK * Dc;
static const size_t H_K    = H_Q   + (size_t)NTOK * Dc;
static const size_t H_VT   = H_K   + (size_t)NTOK * Dc;     // [B,H,DH,S]
static const size_t H_CTX  = H_VT  + (size_t)NTOK * Dc;
static const size_t H_INT  = H_CTX + (size_t)NTOK * Dc;
static const size_t H_HB   = H_INT + (size_t)NTOK * Dc;     // 4096*4096
static const size_t H_PR   = H_HB  + (size_t)NTOK * Fc;     // probs B*H*S*S
static const size_t H_WQ   = H_PR  + (size_t)Bc * Hc * Sc * Sc;
static const size_t H_WK   = H_WQ  + (size_t)Dc * Dc;
static const size_t H_WV   = H_WK  + (size_t)Dc * Dc;
static const size_t H_WO   = H_WV  + (size_t)Dc * Dc;
static const size_t H_W1   = H_WO  + (size_t)Dc * Dc;       // [E][N=F,K=D]
static const size_t H_W2   = H_W1  + (size_t)Ec * Dc * Fc;  // [E][N=D,K=F]
static const size_t H_TOTAL= H_W2  + (size_t)Ec * Fc * Dc;
__device__ __half g_f16[H_TOTAL];

// ---------------- PTX helpers (sm_100-safe: mma.sync / ldmatrix / cp.async) --
__device__ __forceinline__ uint32_t smem_u32(const void* p) {
    uint32_t a;
    asm("{ .reg .u64 t; cvta.to.shared.u64 t, %1; cvt.u32.u64 %0, t; }" : "=r"(a) : "l"(p));
    return a;
}
__device__ __forceinline__ void cp16(uint32_t s, const void* g) {
    asm volatile("cp.async.cg.shared.global [%0], [%1], 16;" :: "r"(s), "l"(g));
}
#define CP_COMMIT() asm volatile("cp.async.commit_group;" ::: "memory")
#define CP_WAIT(n)  asm volatile("cp.async.wait_group %0;" :: "n"(n) : "memory")

__device__ __forceinline__ void ldm_x4(uint32_t* r, uint32_t addr) {
    asm volatile("ldmatrix.sync.aligned.m8n8.x4.shared.b16 {%0,%1,%2,%3}, [%4];"
        : "=r"(r[0]), "=r"(r[1]), "=r"(r[2]), "=r"(r[3]) : "r"(addr));
}
__device__ __forceinline__ void mma16816(float* c, const uint32_t* a, const uint32_t* b) {
    asm volatile(
        "mma.sync.aligned.m16n8k16.row.col.f32.f16.f16.f32 "
        "{%0,%1,%2,%3}, {%4,%5,%6,%7}, {%8,%9}, {%0,%1,%2,%3};"
        : "+f"(c[0]), "+f"(c[1]), "+f"(c[2]), "+f"(c[3])
        : "r"(a[0]), "r"(a[1]), "r"(a[2]), "r"(a[3]), "r"(b[0]), "r"(b[1]));
}

__device__ __forceinline__ float gelu_tanh(float x) {
    float x3 = x * x * x;
    float t  = tanhf(0.7978845608028654f * (x + 0.044715f * x3));
    return 0.5f * x * (1.0f + t);
}
__device__ __forceinline__ uint32_t pack_h2(float a, float b) {
    __half2 h = __floats2half2_rn(a, b);
    return *reinterpret_cast<uint32_t*>(&h);
}

// ============================================================================
// HMMA GEMM: C[M, N-tiles of NT] = A[M,K] * B[N,K]^T   (A,B fp16, K-major)
// CTA tile 128 x NT, BK=32, 256 threads = 8 warps (4 along M x 2 along N).
// Warp tile 32 x (NT/2). mma.m16n8k16, double-buffered cp.async.
// EPI: 0 = fp32 C = acc + bias?          3 = fp32 C = acc*alpha + mask
//      1 = fp16 C16 = gelu(acc + bias)   6 = fp16 C16 = acc + bias?
//      2 = fp32 C = gate*(acc+bias)      5 = fp32 C += gate*(acc+bias)
//      7 = fp16 V^T scatter: acc + bias -> C16[b,h,d,s]
// Batched over blockIdx.z (z = bb*Hdim + hh) via element offsets.
// ============================================================================
#define SPAD 40          // smem row stride in halves (80 bytes)

template <int NT, int EPI>
__global__ __launch_bounds__(256)
void hgemm(const __half* __restrict__ A, const __half* __restrict__ B,
           float* __restrict__ C, __half* __restrict__ C16,
           const float* __restrict__ bias, const float* __restrict__ aux,
           int K, int lda, int ldb, int ldc, int ldaux, float alpha, int Hdim,
           long long aOB, long long aOH, long long bOB, long long bOH,
           long long cOB, long long cOH, long long xOB)
{
    __shared__ __half As[2][128][SPAD];
    __shared__ __half Bs[2][NT][SPAD];

    const int tid = threadIdx.x, wid = tid >> 5, lane = tid & 31;
    const int wm = wid & 3, wn = wid >> 2;          // warp grid 4 x 2
    const int WN = NT / 2;                          // warp N extent
    const int NF = WN / 8;                          // n-fragments per warp

    const int m0 = blockIdx.y * 128, n0 = blockIdx.x * NT;
    const int z = blockIdx.z, bb = z / Hdim, hh = z - bb * Hdim;
    A += (size_t)bb * aOB + (size_t)hh * aOH;
    B += (size_t)bb * bOB + (size_t)hh * bOH;
    const long long coff = (long long)bb * cOB + (long long)hh * cOH;

    const uint32_t abase = smem_u32(&As[0][0][0]);
    const uint32_t bbase = smem_u32(&Bs[0][0][0]);
    const uint32_t ABUF = 128 * SPAD * 2;           // bytes per A buffer
    const uint32_t BBUF = (uint32_t)NT * SPAD * 2;  // bytes per B buffer

    float acc[2][8][4];
#pragma unroll
    for (int i = 0; i < 2; i++)
#pragma unroll
        for (int j = 0; j < 8; j++)
#pragma unroll
            for (int r = 0; r < 4; r++) acc[i][j][r] = 0.0f;

    const int nc = K >> 5;  // BK = 32

    // ---- tile loader (tile c into buffer buf) via cp.async
    auto load_tile = [&](int c, int buf) {
        const __half* Ab = A + (size_t)m0 * lda + (size_t)c * 32;
#pragma unroll
        for (int it = 0; it < 2; it++) {
            int lin = it * 256 + tid;
            int row = lin >> 2, seg = lin & 3;
            cp16(abase + buf * ABUF + row * (SPAD * 2) + seg * 16,
                 Ab + (size_t)row * lda + seg * 8);
        }
        const __half* Bb = B + (size_t)n0 * ldb + (size_t)c * 32;
#pragma unroll
        for (int it = 0; it < (NT * 4) / 256; it++) {
            int lin = it * 256 + tid;
            int row = lin >> 2, seg = lin & 3;
            cp16(bbase + buf * BBUF + row * (SPAD * 2) + seg * 16,
                 Bb + (size_t)row * ldb + seg * 8);
        }
    };

    load_tile(0, 0);
    CP_COMMIT();

    for (int c = 0; c < nc; c++) {
        const int buf = c & 1;
        __syncthreads();                       // protect buf^1 before overwrite
        if (c + 1 < nc) { load_tile(c + 1, buf ^ 1); CP_COMMIT(); }
        if (c + 1 < nc) { CP_WAIT(1); } else { CP_WAIT(0); }
        __syncthreads();

#pragma unroll
        for (int ks = 0; ks < 2; ks++) {
            // A fragments: 2 x 16x16
            uint32_t af[2][4];
#pragma unroll
            for (int mi = 0; mi < 2; mi++) {
                int row = wm * 32 + mi * 16 + (lane & 15);
                int col = ks * 16 + (lane >> 4) * 8;
                ldm_x4(af[mi], abase + buf * ABUF + row * (SPAD * 2) + col * 2);
            }
            // B fragments: NF x (k16 x n8), loaded in pairs
            uint32_t bf[8][2];
#pragma unroll
            for (int p = 0; p < NF / 2; p++) {
                int row = wn * WN + p * 16 + (lane & 7) + ((lane >> 4) << 3);
                int col = ks * 16 + ((lane >> 3) & 1) * 8;
                uint32_t t[4];
                ldm_x4(t, bbase + buf * BBUF + row * (SPAD * 2) + col * 2);
                bf[2 * p][0] = t[0]; bf[2 * p][1] = t[1];
                bf[2 * p + 1][0] = t[2]; bf[2 * p + 1][1] = t[3];
            }
#pragma unroll
            for (int mi = 0; mi < 2; mi++)
#pragma unroll
                for (int nj = 0; nj < 8; nj++)
                    if (nj < NF) mma16816(acc[mi][nj], af[mi], bf[nj]);
        }
    }

    // -------- epilogue --------
#pragma unroll
    for (int mi = 0; mi < 2; mi++) {
#pragma unroll
        for (int nj = 0; nj < 8; nj++) {
            if (nj >= NF) continue;
            const int r0 = m0 + wm * 32 + mi * 16 + (lane >> 2);
            const int cc = n0 + wn * WN + nj * 8 + (lane & 3) * 2;
#pragma unroll
            for (int h = 0; h < 2; h++) {
                const int row = r0 + h * 8;
                const float v0 = acc[mi][nj][2 * h + 0];
                const float v1 = acc[mi][nj][2 * h + 1];
                if (EPI == 0) {
                    float b0 = bias ? bias[cc] : 0.f, b1 = bias ? bias[cc + 1] : 0.f;
                    float2 o = make_float2(v0 + b0, v1 + b1);
                    *(float2*)(C + coff + (size_t)row * ldc + cc) = o;
                } else if (EPI == 3) {
                    const float* mp = aux + (size_t)bb * xOB + (size_t)row * ldaux + cc;
                    float2 o = make_float2(v0 * alpha + mp[0], v1 * alpha + mp[1]);
                    *(float2*)(C + coff + (size_t)row * ldc + cc) = o;
                } else if (EPI == 2 || EPI == 5) {
                    const float gt = aux[(size_t)row * ldaux];
                    float* cp = C + coff + (size_t)row * ldc + cc;
                    float2 o = (EPI == 5) ? *(float2*)cp : make_float2(0.f, 0.f);
                    o.x += gt * (v0 + bias[cc]);
                    o.y += gt * (v1 + bias[cc + 1]);
                    *(float2*)cp = o;
                } else if (EPI == 1 || EPI == 6) {
                    float o0 = v0 + (bias ? bias[cc] : 0.f);
                    float o1 = v1 + (bias ? bias[cc + 1] : 0.f);
                    if (EPI == 1) { o0 = gelu_tanh(o0); o1 = gelu_tanh(o1); }
                    *(uint32_t*)(C16 + coff + (size_t)row * ldc + cc) = pack_h2(o0, o1);
                } else if (EPI == 7) {
                    const int b_ = row >> 11, s_ = row & 2047;
                    float o0 = v0 + (bias ? bias[cc] : 0.f);
                    float o1 = v1 + (bias ? bias[cc + 1] : 0.f);
                    const int h0 = cc >> 6, d0 = cc & 63;
                    const int h1 = (cc + 1) >> 6, d1 = (cc + 1) & 63;
                    C16[((size_t)((b_ * Hc + h0) * DHc + d0)) * Sc + s_] = __float2half(o0);
                    C16[((size_t)((b_ * Hc + h1) * DHc + d1)) * Sc + s_] = __float2half(o1);
                }
            }
        }
    }
}

// ---------------- fp32 -> fp16 convert ----------------
__global__ void conv16(const float* __restrict__ s, __half* __restrict__ d, int n4)
{
    int i = blockIdx.x * blockDim.x + threadIdx.x;
    if (i < n4) {
        float4 v = ((const float4*)s)[i];
        uint2 u;
        u.x = pack_h2(v.x, v.y); u.y = pack_h2(v.z, v.w);
        ((uint2*)d)[i] = u;
    }
}

// ---------------- transpose-convert: src [K,N] f32 -> dst [N,K] f16 --------
__global__ void tconv(const float* __restrict__ src, __half* __restrict__ dst, int K, int N)
{
    __shared__ float t[32][33];
    src += (size_t)blockIdx.z * K * N;
    dst += (size_t)blockIdx.z * K * N;
    const int k0 = blockIdx.y * 32, n0 = blockIdx.x * 32;
    const int x = threadIdx.x, y = threadIdx.y;
#pragma unroll
    for (int i = 0; i < 32; i += 8)
        t[y + i][x] = src[(size_t)(k0 + y + i) * N + n0 + x];
    __syncthreads();
#pragma unroll
    for (int i = 0; i < 32; i += 8)
        dst[(size_t)(n0 + y + i) * K + k0 + x] = __float2half(t[x][y + i]);
}

// ---------------- softmax over rows of length 2048, fp32 in -> fp16 out ----
__global__ void softmax2048(const float* __restrict__ sc, __half* __restrict__ pr)
{
    __shared__ float red[256];
    const size_t base = (size_t)blockIdx.x * 2048;
    const int tid = threadIdx.x;
    float v[8];
    float mx = -INFINITY;
#pragma unroll
    for (int i = 0; i < 8; i++) { v[i] = sc[base + tid + i * 256]; mx = fmaxf(mx, v[i]); }
    red[tid] = mx; __syncthreads();
    for (int s = 128; s > 0; s >>= 1) { if (tid < s) red[tid] = fmaxf(red[tid], red[tid + s]); __syncthreads(); }
    mx = red[0]; __syncthreads();
    float sum = 0.f;
#pragma unroll
    for (int i = 0; i < 8; i++) { v[i] = expf(v[i] - mx); sum += v[i]; }
    red[tid] = sum; __syncthreads();
    for (int s = 128; s > 0; s >>= 1) { if (tid < s) red[tid] += red[tid + s]; __syncthreads(); }
    const float inv = 1.0f / red[0];
#pragma unroll
    for (int i = 0; i < 8; i++) pr[base + tid + i * 256] = __float2half(v[i] * inv);
}

// ---------------- LayerNorm(x + r), fp32 out + optional fp16 copy ----------
__global__ void ln_residual(const float* __restrict__ x, const float* __restrict__ r,
                            const float* __restrict__ g, const float* __restrict__ b,
                            float* __restrict__ out, __half* __restrict__ out16)
{
    __shared__ float red[256];
    const size_t base = (size_t)blockIdx.x * Dc;
    const int tid = threadIdx.x;
    float v[4]; float s = 0.f;
#pragma unroll
    for (int i = 0; i < 4; i++) { const int c = tid + i * 256; v[i] = x[base + c] + r[base + c]; s += v[i]; }
    red[tid] = s; __syncthreads();
    for (int st = 128; st > 0; st >>= 1) { if (tid < st) red[tid] += red[tid + st]; __syncthreads(); }
    const float mean = red[0] * (1.0f / Dc); __syncthreads();
    float ss = 0.f;
#pragma unroll
    for (int i = 0; i < 4; i++) { const float d = v[i] - mean; ss += d * d; }
    red[tid] = ss; __syncthreads();
    for (int st = 128; st > 0; st >>= 1) { if (tid < st) red[tid] += red[tid + st]; __syncthreads(); }
    const float rstd = rsqrtf(red[0] * (1.0f / Dc) + LN_EPS);
#pragma unroll
    for (int i = 0; i < 4; i++) {
        const int c = tid + i * 256;
        const float o = (v[i] - mean) * rstd * g[c] + b[c];
        out[base + c] = o;
        if (out16) out16[base + c] = __float2half(o);
    }
}

// ---------------- gate: softmax(x @ gate_w + gate_b) over E=8 --------------
__global__ void gate_kernel(const float* __restrict__ x, const float* __restrict__ gw,
                            const float* __restrict__ gb,
                            float* __restrict__ gate, float* __restrict__ gate_out)
{
    const int m = blockIdx.x;
    const int tid = threadIdx.x;
    const int wid = tid >> 5, lane = tid & 31;
    __shared__ float logits[Ec];
    float s = 0.f;
    const float* xr = x + (size_t)m * Dc;
    for (int d = lane; d < Dc; d += 32) s += xr[d] * gw[d * Ec + wid];
#pragma unroll
    for (int o = 16; o > 0; o >>= 1) s += __shfl_down_sync(0xffffffffu, s, o);
    if (lane == 0) logits[wid] = s + gb[wid];
    __syncthreads();
    if (tid == 0) {
        float mx = logits[0];
#pragma unroll
        for (int e = 1; e < Ec; e++) mx = fmaxf(mx, logits[e]);
        float p[Ec]; float sum = 0.f;
#pragma unroll
        for (int e = 0; e < Ec; e++) { p[e] = expf(logits[e] - mx); sum += p[e]; }
        const float inv = 1.0f / sum;
#pragma unroll
        for (int e = 0; e < Ec; e++) {
            const float pv = p[e] * inv;
            gate[(size_t)m * Ec + e] = pv;
            if (gate_out) gate_out[(size_t)m * Ec + e] = pv;
        }
    }
}

// ---------------- launch ----------------------------------------------------
extern "C" void kernel_launch(void* const* d_in, const int* in_sizes, int n_in,
                              void* d_out, int out_size)
{
    const float* hidden = (const float*)d_in[0];
    const float* mask   = (const float*)d_in[1];
    const float* wq = (const float*)d_in[2];  const float* bq = (const float*)d_in[3];
    const float* wk = (const float*)d_in[4];  const float* bk = (const float*)d_in[5];
    const float* wv = (const float*)d_in[6];  const float* bv = (const float*)d_in[7];
    const float* wo = (const float*)d_in[8];  const float* bo = (const float*)d_in[9];
    const float* ln1_g = (const float*)d_in[10]; const float* ln1_b = (const float*)d_in[11];
    const float* gate_w = (const float*)d_in[12]; const float* gate_b = (const float*)d_in[13];
    const float* w1 = (const float*)d_in[14]; const float* b1 = (const float*)d_in[15];
    const float* w2 = (const float*)d_in[16]; const float* b2 = (const float*)d_in[17];
    const float* ln2_g = (const float*)d_in[18]; const float* ln2_b = (const float*)d_in[19];

    float* f32 = nullptr;  __half* f16 = nullptr;
    cudaGetSymbolAddress((void**)&f32, g_f32);
    cudaGetSymbolAddress((void**)&f16, g_f16);

    float*  scores = f32 + F_SC;
    float*  attn   = f32 + F_ATTN;
    float*  inter  = f32 + F_INT;
    float*  moe    = f32 + F_MOE;
    float*  gate   = f32 + F_GATE;
    __half* hid16  = f16 + H_HID;
    __half* q16    = f16 + H_Q;
    __half* k16    = f16 + H_K;
    __half* vT16   = f16 + H_VT;
    __half* ctx16  = f16 + H_CTX;
    __half* int16_ = f16 + H_INT;
    __half* h16    = f16 + H_HB;
    __half* pr16   = f16 + H_PR;
    __half* wqT = f16 + H_WQ; __half* wkT = f16 + H_WK;
    __half* wvT = f16 + H_WV; __half* woT = f16 + H_WO;
    __half* w1T = f16 + H_W1; __half* w2T = f16 + H_W2;

    float* out = (float*)d_out;
    float* gate_out = nullptr;
    if ((size_t)out_size >= (size_t)NTOK * Dc + (size_t)NTOK * Ec)
        gate_out = out + (size_t)NTOK * Dc;

    const dim3 blk(256);
    const dim3 tblk(32, 8);

    // 0) conversions
    conv16<<<(NTOK * Dc / 4 + 255) / 256, 256>>>(hidden, hid16, NTOK * Dc / 4);
    tconv<<<dim3(Dc / 32, Dc / 32, 1), tblk>>>(wq, wqT, Dc, Dc);
    tconv<<<dim3(Dc / 32, Dc / 32, 1), tblk>>>(wk, wkT, Dc, Dc);
    tconv<<<dim3(Dc / 32, Dc / 32, 1), tblk>>>(wv, wvT, Dc, Dc);
    tconv<<<dim3(Dc / 32, Dc / 32, 1), tblk>>>(wo, woT, Dc, Dc);
    tconv<<<dim3(Fc / 32, Dc / 32, Ec), tblk>>>(w1, w1T, Dc, Fc);
    tconv<<<dim3(Dc / 32, Fc / 32, Ec), tblk>>>(w2, w2T, Fc, Dc);

    // 1) Q/K projections -> fp16; V projection -> vT (transposed scatter)
    {
        dim3 grid(Dc / 128, NTOK / 128, 1);
        hgemm<128,6><<<grid, blk>>>(hid16, wqT, nullptr, q16, bq, nullptr,
            Dc, Dc, Dc, Dc, 0, 0.f, 1, 0,0,0,0,0,0,0);
        hgemm<128,6><<<grid, blk>>>(hid16, wkT, nullptr, k16, bk, nullptr,
            Dc, Dc, Dc, Dc, 0, 0.f, 1, 0,0,0,0,0,0,0);
        hgemm<128,7><<<grid, blk>>>(hid16, wvT, nullptr, vT16, bv, nullptr,
            Dc, Dc, Dc, Dc, 0, 0.f, 1, 0,0,0,0,0,0,0);
    }

    // 2) scores = QK^T/8 + mask (per b,h; K=64)
    {
        dim3 grid(Sc / 128, Sc / 128, Bc * Hc);
        hgemm<128,3><<<grid, blk>>>(q16, k16, scores, nullptr, nullptr, mask,
            DHc, Dc, Dc, Sc, Sc, 0.125f, Hc,
            (long long)Sc * Dc, DHc,
            (long long)Sc * Dc, DHc,
            (long long)Hc * Sc * Sc, (long long)Sc * Sc,
            (long long)Sc * Sc);
    }

    // 3) softmax -> fp16 probs
    softmax2048<<<Bc * Hc * Sc, 256>>>(scores, pr16);

    // 4) ctx = probs @ V   (B operand = vT [DH,S] rows, N=64 per head)
    {
        dim3 grid(1, Sc / 128, Bc * Hc);
        hgemm<64,6><<<grid, blk>>>(pr16, vT16, nullptr, ctx16, nullptr, nullptr,
            Sc, Sc, Sc, Dc, 0, 0.f, Hc,
            (long long)Hc * Sc * Sc, (long long)Sc * Sc,
            (long long)Hc * DHc * Sc, (long long)DHc * Sc,
            (long long)Sc * Dc, (long long)DHc, 0);
    }

    // 5) output projection -> fp32 attn
    {
        dim3 grid(Dc / 128, NTOK / 128, 1);
        hgemm<128,0><<<grid, blk>>>(ctx16, woT, attn, nullptr, bo, nullptr,
            Dc, Dc, Dc, Dc, 0, 0.f, 1, 0,0,0,0,0,0,0);
    }

    // 6) inter = LN1(attn + hidden)  (fp32 + fp16)
    ln_residual<<<NTOK, 256>>>(attn, hidden, ln1_g, ln1_b, inter, int16_);

    // 7) gate
    gate_kernel<<<NTOK, 256>>>(inter, gate_w, gate_b, gate, gate_out);

    // 8) MoE
    for (int e = 0; e < Ec; e++) {
        dim3 gh(Fc / 128, NTOK / 128, 1);
        hgemm<128,1><<<gh, blk>>>(int16_, w1T + (size_t)e * Dc * Fc,
            nullptr, h16, b1 + (size_t)e * Fc, nullptr,
            Dc, Dc, Dc, Fc, 0, 0.f, 1, 0,0,0,0,0,0,0);

        dim3 gy(Dc / 128, NTOK / 128, 1);
        if (e == 0)
            hgemm<128,2><<<gy, blk>>>(h16, w2T + (size_t)e * Fc * Dc,
                moe, nullptr, b2 + (size_t)e * Dc, gate + e,
                Fc, Fc, Fc, Dc, Ec, 0.f, 1, 0,0,0,0,0,0,0);
        else
            hgemm<128,5><<<gy, blk>>>(h16, w2T + (size_t)e * Fc * Dc,
                moe, nullptr, b2 + (size_t)e * Dc, gate + e,
                Fc, Fc, Fc, Dc, Ec, 0.f, 1, 0,0,0,0,0,0,0);
    }

    // 9) output = LN2(moe + inter)
    ln_residual<<<NTOK, 256>>>(moe, inter, ln2_g, ln2_b, out, nullptr);
}

// round 4
// speedup vs baseline: 5.8544x; 1.0700x over previous
#include <cuda_runtime.h>
#include <cuda_fp16.h>
#include <math.h>
#include <stdint.h>

// ---------------- problem constants ----------------
#define Bc 2
#define Sc 2048
#define Dc 1024
#define Hc 16
#define DHc 64
#define Fc 4096
#define Ec 8
#define NTOK (Bc * Sc)
#define LN_EPS 1e-6f

// ---------------- fp32 scratch ----------------
static const size_t F_SC    = 0;                                   // scores  B*H*S*S
static const size_t F_ATTN  = F_SC  + (size_t)Bc * Hc * Sc * Sc;
static const size_t F_INT   = F_ATTN + (size_t)NTOK * Dc;
static const size_t F_MOE   = F_INT  + (size_t)NTOK * Dc;
static const size_t F_GATE  = F_MOE  + (size_t)NTOK * Dc;
static const size_t F_TOTAL = F_GATE + (size_t)NTOK * Ec;
__device__ float g_f32[F_TOTAL];

// ---------------- fp16 scratch ----------------
static const size_t H_HID  = 0;
static const size_t H_Q    = H_HID + (size_t)NTOK * Dc;
static const size_t H_K    = H_Q   + (size_t)NTOK * Dc;
static const size_t H_VT   = H_K   + (size_t)NTOK * Dc;     // [B,H,DH,S]
static const size_t H_CTX  = H_VT  + (size_t)NTOK * Dc;
static const size_t H_INT  = H_CTX + (size_t)NTOK * Dc;
static const size_t H_HB   = H_INT + (size_t)NTOK * Dc;     // 4096*4096
static const size_t H_PR   = H_HB  + (size_t)NTOK * Fc;     // probs B*H*S*S
static const size_t H_WQ   = H_PR  + (size_t)Bc * Hc * Sc * Sc;
static const size_t H_WK   = H_WQ  + (size_t)Dc * Dc;
static const size_t H_WV   = H_WK  + (size_t)Dc * Dc;
static const size_t H_WO   = H_WV  + (size_t)Dc * Dc;
static const size_t H_W1   = H_WO  + (size_t)Dc * Dc;       // [E][N=F,K=D]
static const size_t H_W2   = H_W1  + (size_t)Ec * Dc * Fc;  // [E][N=D,K=F]
static const size_t H_TOTAL= H_W2  + (size_t)Ec * Fc * Dc;
__device__ __half g_f16[H_TOTAL];

// ---------------- PTX helpers (sm_100-safe: mma.sync / ldmatrix / cp.async) --
__device__ __forceinline__ uint32_t smem_u32(const void* p) {
    uint32_t a;
    asm("{ .reg .u64 t; cvta.to.shared.u64 t, %1; cvt.u32.u64 %0, t; }" : "=r"(a) : "l"(p));
    return a;
}
__device__ __forceinline__ void cp16(uint32_t s, const void* g) {
    asm volatile("cp.async.cg.shared.global [%0], [%1], 16;" :: "r"(s), "l"(g));
}
#define CP_COMMIT() asm volatile("cp.async.commit_group;" ::: "memory")
#define CP_WAIT(n)  asm volatile("cp.async.wait_group %0;" :: "n"(n) : "memory")

__device__ __forceinline__ void ldm_x4(uint32_t* r, uint32_t addr) {
    asm volatile("ldmatrix.sync.aligned.m8n8.x4.shared.b16 {%0,%1,%2,%3}, [%4];"
        : "=r"(r[0]), "=r"(r[1]), "=r"(r[2]), "=r"(r[3]) : "r"(addr));
}
__device__ __forceinline__ void mma16816(float* c, const uint32_t* a, const uint32_t* b) {
    asm volatile(
        "mma.sync.aligned.m16n8k16.row.col.f32.f16.f16.f32 "
        "{%0,%1,%2,%3}, {%4,%5,%6,%7}, {%8,%9}, {%0,%1,%2,%3};"
        : "+f"(c[0]), "+f"(c[1]), "+f"(c[2]), "+f"(c[3])
        : "r"(a[0]), "r"(a[1]), "r"(a[2]), "r"(a[3]), "r"(b[0]), "r"(b[1]));
}

__device__ __forceinline__ float gelu_tanh(float x) {
    float x3 = x * x * x;
    float t  = tanhf(0.7978845608028654f * (x + 0.044715f * x3));
    return 0.5f * x * (1.0f + t);
}
__device__ __forceinline__ uint32_t pack_h2(float a, float b) {
    __half2 h = __floats2half2_rn(a, b);
    return *reinterpret_cast<uint32_t*>(&h);
}

// ============================================================================
// HMMA GEMM: C[M, N-tiles of NT] = A[M,K] * B[N,K]^T   (A,B fp16, K-major)
// CTA tile 128 x NT, BK=32, 256 threads = 8 warps (4 along M x 2 along N).
// Warp tile 32 x (NT/2). mma.m16n8k16.
// 4-stage cp.async pipeline, ONE __syncthreads per K-chunk.
// EPI: 0 = fp32 C = acc + bias?          3 = fp32 C = acc*alpha + mask
//      1 = fp16 C16 = gelu(acc + bias)   6 = fp16 C16 = acc + bias?
//      2 = fp32 C = gate*(acc+bias)      5 = fp32 C += gate*(acc+bias)
//      7 = fp16 V^T scatter: acc + bias -> C16[b,h,d,s]
// ============================================================================
#define SPAD 40          // smem row stride in halves (80 bytes)
#define STAGES 4

template <int NT, int EPI>
__global__ __launch_bounds__(256)
void hgemm(const __half* __restrict__ A, const __half* __restrict__ B,
           float* __restrict__ C, __half* __restrict__ C16,
           const float* __restrict__ bias, const float* __restrict__ aux,
           int K, int lda, int ldb, int ldc, int ldaux, float alpha, int Hdim,
           long long aOB, long long aOH, long long bOB, long long bOH,
           long long cOB, long long cOH, long long xOB)
{
    extern __shared__ __half smem[];

    const int tid = threadIdx.x, wid = tid >> 5, lane = tid & 31;
    const int wm = wid & 3, wn = wid >> 2;          // warp grid 4 x 2
    const int WN = NT / 2;                          // warp N extent
    const int NF = WN / 8;                          // n-fragments per warp

    const int m0 = blockIdx.y * 128, n0 = blockIdx.x * NT;
    const int z = blockIdx.z, bb = z / Hdim, hh = z - bb * Hdim;
    A += (size_t)bb * aOB + (size_t)hh * aOH;
    B += (size_t)bb * bOB + (size_t)hh * bOH;
    const long long coff = (long long)bb * cOB + (long long)hh * cOH;

    const uint32_t ABUF = 128 * SPAD * 2;                 // bytes per A stage
    const uint32_t BBUF = (uint32_t)NT * SPAD * 2;        // bytes per B stage
    const uint32_t abase = smem_u32(smem);
    const uint32_t bbase = abase + STAGES * ABUF;

    float acc[2][8][4];
#pragma unroll
    for (int i = 0; i < 2; i++)
#pragma unroll
        for (int j = 0; j < 8; j++)
#pragma unroll
            for (int r = 0; r < 4; r++) acc[i][j][r] = 0.0f;

    const int nc = K >> 5;  // BK = 32

    // ---- tile loader (tile c into stage buf) via cp.async
    auto load_tile = [&](int c, int buf) {
        const __half* Ab = A + (size_t)m0 * lda + (size_t)c * 32;
#pragma unroll
        for (int it = 0; it < 2; it++) {
            int lin = it * 256 + tid;
            int row = lin >> 2, seg = lin & 3;
            cp16(abase + buf * ABUF + row * (SPAD * 2) + seg * 16,
                 Ab + (size_t)row * lda + seg * 8);
        }
        const __half* Bb = B + (size_t)n0 * ldb + (size_t)c * 32;
#pragma unroll
        for (int it = 0; it < (NT * 4) / 256; it++) {
            int lin = it * 256 + tid;
            int row = lin >> 2, seg = lin & 3;
            cp16(bbase + buf * BBUF + row * (SPAD * 2) + seg * 16,
                 Bb + (size_t)row * ldb + seg * 8);
        }
    };

    // ---- prologue: fill STAGES-1 stages
#pragma unroll
    for (int s = 0; s < STAGES - 1; s++) {
        if (s < nc) load_tile(s, s);
        CP_COMMIT();
    }

    for (int c = 0; c < nc; c++) {
        CP_WAIT(STAGES - 2);               // tile c resident
        __syncthreads();                   // all warps done with stage (c-1)%STAGES
        const int nxt = c + STAGES - 1;
        if (nxt < nc) load_tile(nxt, nxt % STAGES);
        CP_COMMIT();                       // always commit (tail = empty groups)

        const int buf = c % STAGES;
        const uint32_t ab = abase + buf * ABUF;
        const uint32_t bbf = bbase + buf * BBUF;

#pragma unroll
        for (int ks = 0; ks < 2; ks++) {
            // A fragments: 2 x 16x16
            uint32_t af[2][4];
#pragma unroll
            for (int mi = 0; mi < 2; mi++) {
                int row = wm * 32 + mi * 16 + (lane & 15);
                int col = ks * 16 + (lane >> 4) * 8;
                ldm_x4(af[mi], ab + row * (SPAD * 2) + col * 2);
            }
            // B fragments: NF x (k16 x n8), loaded in pairs
            uint32_t bf[8][2];
#pragma unroll
            for (int p = 0; p < NF / 2; p++) {
                int row = wn * WN + p * 16 + (lane & 7) + ((lane >> 4) << 3);
                int col = ks * 16 + ((lane >> 3) & 1) * 8;
                uint32_t t[4];
                ldm_x4(t, bbf + row * (SPAD * 2) + col * 2);
                bf[2 * p][0] = t[0]; bf[2 * p][1] = t[1];
                bf[2 * p + 1][0] = t[2]; bf[2 * p + 1][1] = t[3];
            }
#pragma unroll
            for (int mi = 0; mi < 2; mi++)
#pragma unroll
                for (int nj = 0; nj < 8; nj++)
                    if (nj < NF) mma16816(acc[mi][nj], af[mi], bf[nj]);
        }
    }

    // -------- epilogue --------
#pragma unroll
    for (int mi = 0; mi < 2; mi++) {
#pragma unroll
        for (int nj = 0; nj < 8; nj++) {
            if (nj >= NF) continue;
            const int r0 = m0 + wm * 32 + mi * 16 + (lane >> 2);
            const int cc = n0 + wn * WN + nj * 8 + (lane & 3) * 2;
#pragma unroll
            for (int h = 0; h < 2; h++) {
                const int row = r0 + h * 8;
                const float v0 = acc[mi][nj][2 * h + 0];
                const float v1 = acc[mi][nj][2 * h + 1];
                if (EPI == 0) {
                    float b0 = bias ? bias[cc] : 0.f, b1 = bias ? bias[cc + 1] : 0.f;
                    float2 o = make_float2(v0 + b0, v1 + b1);
                    *(float2*)(C + coff + (size_t)row * ldc + cc) = o;
                } else if (EPI == 3) {
                    const float* mp = aux + (size_t)bb * xOB + (size_t)row * ldaux + cc;
                    float2 o = make_float2(v0 * alpha + mp[0], v1 * alpha + mp[1]);
                    *(float2*)(C + coff + (size_t)row * ldc + cc) = o;
                } else if (EPI == 2 || EPI == 5) {
                    const float gt = aux[(size_t)row * ldaux];
                    float* cp = C + coff + (size_t)row * ldc + cc;
                    float2 o = (EPI == 5) ? *(float2*)cp : make_float2(0.f, 0.f);
                    o.x += gt * (v0 + bias[cc]);
                    o.y += gt * (v1 + bias[cc + 1]);
                    *(float2*)cp = o;
                } else if (EPI == 1 || EPI == 6) {
                    float o0 = v0 + (bias ? bias[cc] : 0.f);
                    float o1 = v1 + (bias ? bias[cc + 1] : 0.f);
                    if (EPI == 1) { o0 = gelu_tanh(o0); o1 = gelu_tanh(o1); }
                    *(uint32_t*)(C16 + coff + (size_t)row * ldc + cc) = pack_h2(o0, o1);
                } else if (EPI == 7) {
                    const int b_ = row >> 11, s_ = row & 2047;
                    float o0 = v0 + (bias ? bias[cc] : 0.f);
                    float o1 = v1 + (bias ? bias[cc + 1] : 0.f);
                    const int h0 = cc >> 6, d0 = cc & 63;
                    const int h1 = (cc + 1) >> 6, d1 = (cc + 1) & 63;
                    C16[((size_t)((b_ * Hc + h0) * DHc + d0)) * Sc + s_] = __float2half(o0);
                    C16[((size_t)((b_ * Hc + h1) * DHc + d1)) * Sc + s_] = __float2half(o1);
                }
            }
        }
    }
}

static const int SMEM_NT128 = STAGES * (128 * SPAD * 2 + 128 * SPAD * 2);  // 81920
static const int SMEM_NT64  = STAGES * (128 * SPAD * 2 +  64 * SPAD * 2);  // 61440

// ---------------- fp32 -> fp16 convert ----------------
__global__ void conv16(const float* __restrict__ s, __half* __restrict__ d, int n4)
{
    int i = blockIdx.x * blockDim.x + threadIdx.x;
    if (i < n4) {
        float4 v = ((const float4*)s)[i];
        uint2 u;
        u.x = pack_h2(v.x, v.y); u.y = pack_h2(v.z, v.w);
        ((uint2*)d)[i] = u;
    }
}

// ---------------- transpose-convert: src [K,N] f32 -> dst [N,K] f16 --------
__global__ void tconv(const float* __restrict__ src, __half* __restrict__ dst, int K, int N)
{
    __shared__ float t[32][33];
    src += (size_t)blockIdx.z * K * N;
    dst += (size_t)blockIdx.z * K * N;
    const int k0 = blockIdx.y * 32, n0 = blockIdx.x * 32;
    const int x = threadIdx.x, y = threadIdx.y;
#pragma unroll
    for (int i = 0; i < 32; i += 8)
        t[y + i][x] = src[(size_t)(k0 + y + i) * N + n0 + x];
    __syncthreads();
#pragma unroll
    for (int i = 0; i < 32; i += 8)
        dst[(size_t)(n0 + y + i) * K + k0 + x] = __float2half(t[x][y + i]);
}

// ---------------- softmax over rows of length 2048, fp32 in -> fp16 out ----
__global__ void softmax2048(const float* __restrict__ sc, __half* __restrict__ pr)
{
    __shared__ float red[256];
    const size_t base = (size_t)blockIdx.x * 2048;
    const int tid = threadIdx.x;
    float v[8];
    float mx = -INFINITY;
#pragma unroll
    for (int i = 0; i < 8; i++) { v[i] = sc[base + tid + i * 256]; mx = fmaxf(mx, v[i]); }
    red[tid] = mx; __syncthreads();
    for (int s = 128; s > 0; s >>= 1) { if (tid < s) red[tid] = fmaxf(red[tid], red[tid + s]); __syncthreads(); }
    mx = red[0]; __syncthreads();
    float sum = 0.f;
#pragma unroll
    for (int i = 0; i < 8; i++) { v[i] = expf(v[i] - mx); sum += v[i]; }
    red[tid] = sum; __syncthreads();
    for (int s = 128; s > 0; s >>= 1) { if (tid < s) red[tid] += red[tid + s]; __syncthreads(); }
    const float inv = 1.0f / red[0];
#pragma unroll
    for (int i = 0; i < 8; i++) pr[base + tid + i * 256] = __float2half(v[i] * inv);
}

// ---------------- LayerNorm(x + r), fp32 out + optional fp16 copy ----------
__global__ void ln_residual(const float* __restrict__ x, const float* __restrict__ r,
                            const float* __restrict__ g, const float* __restrict__ b,
                            float* __restrict__ out, __half* __restrict__ out16)
{
    __shared__ float red[256];
    const size_t base = (size_t)blockIdx.x * Dc;
    const int tid = threadIdx.x;
    float v[4]; float s = 0.f;
#pragma unroll
    for (int i = 0; i < 4; i++) { const int c = tid + i * 256; v[i] = x[base + c] + r[base + c]; s += v[i]; }
    red[tid] = s; __syncthreads();
    for (int st = 128; st > 0; st >>= 1) { if (tid < st) red[tid] += red[tid + st]; __syncthreads(); }
    const float mean = red[0] * (1.0f / Dc); __syncthreads();
    float ss = 0.f;
#pragma unroll
    for (int i = 0; i < 4; i++) { const float d = v[i] - mean; ss += d * d; }
    red[tid] = ss; __syncthreads();
    for (int st = 128; st > 0; st >>= 1) { if (tid < st) red[tid] += red[tid + st]; __syncthreads(); }
    const float rstd = rsqrtf(red[0] * (1.0f / Dc) + LN_EPS);
#pragma unroll
    for (int i = 0; i < 4; i++) {
        const int c = tid + i * 256;
        const float o = (v[i] - mean) * rstd * g[c] + b[c];
        out[base + c] = o;
        if (out16) out16[base + c] = __float2half(o);
    }
}

// ---------------- gate: softmax(x @ gate_w + gate_b) over E=8 --------------
__global__ void gate_kernel(const float* __restrict__ x, const float* __restrict__ gw,
                            const float* __restrict__ gb,
                            float* __restrict__ gate, float* __restrict__ gate_out)
{
    const int m = blockIdx.x;
    const int tid = threadIdx.x;
    const int wid = tid >> 5, lane = tid & 31;
    __shared__ float logits[Ec];
    float s = 0.f;
    const float* xr = x + (size_t)m * Dc;
    for (int d = lane; d < Dc; d += 32) s += xr[d] * gw[d * Ec + wid];
#pragma unroll
    for (int o = 16; o > 0; o >>= 1) s += __shfl_down_sync(0xffffffffu, s, o);
    if (lane == 0) logits[wid] = s + gb[wid];
    __syncthreads();
    if (tid == 0) {
        float mx = logits[0];
#pragma unroll
        for (int e = 1; e < Ec; e++) mx = fmaxf(mx, logits[e]);
        float p[Ec]; float sum = 0.f;
#pragma unroll
        for (int e = 0; e < Ec; e++) { p[e] = expf(logits[e] - mx); sum += p[e]; }
        const float inv = 1.0f / sum;
#pragma unroll
        for (int e = 0; e < Ec; e++) {
            const float pv = p[e] * inv;
            gate[(size_t)m * Ec + e] = pv;
            if (gate_out) gate_out[(size_t)m * Ec + e] = pv;
        }
    }
}

// ---------------- launch ----------------------------------------------------
extern "C" void kernel_launch(void* const* d_in, const int* in_sizes, int n_in,
                              void* d_out, int out_size)
{
    const float* hidden = (const float*)d_in[0];
    const float* mask   = (const float*)d_in[1];
    const float* wq = (const float*)d_in[2];  const float* bq = (const float*)d_in[3];
    const float* wk = (const float*)d_in[4];  const float* bk = (const float*)d_in[5];
    const float* wv = (const float*)d_in[6];  const float* bv = (const float*)d_in[7];
    const float* wo = (const float*)d_in[8];  const float* bo = (const float*)d_in[9];
    const float* ln1_g = (const float*)d_in[10]; const float* ln1_b = (const float*)d_in[11];
    const float* gate_w = (const float*)d_in[12]; const float* gate_b = (const float*)d_in[13];
    const float* w1 = (const float*)d_in[14]; const float* b1 = (const float*)d_in[15];
    const float* w2 = (const float*)d_in[16]; const float* b2 = (const float*)d_in[17];
    const float* ln2_g = (const float*)d_in[18]; const float* ln2_b = (const float*)d_in[19];

    float* f32 = nullptr;  __half* f16 = nullptr;
    cudaGetSymbolAddress((void**)&f32, g_f32);
    cudaGetSymbolAddress((void**)&f16, g_f16);

    float*  scores = f32 + F_SC;
    float*  attn   = f32 + F_ATTN;
    float*  inter  = f32 + F_INT;
    float*  moe    = f32 + F_MOE;
    float*  gate   = f32 + F_GATE;
    __half* hid16  = f16 + H_HID;
    __half* q16    = f16 + H_Q;
    __half* k16    = f16 + H_K;
    __half* vT16   = f16 + H_VT;
    __half* ctx16  = f16 + H_CTX;
    __half* int16_ = f16 + H_INT;
    __half* h16    = f16 + H_HB;
    __half* pr16   = f16 + H_PR;
    __half* wqT = f16 + H_WQ; __half* wkT = f16 + H_WK;
    __half* wvT = f16 + H_WV; __half* woT = f16 + H_WO;
    __half* w1T = f16 + H_W1; __half* w2T = f16 + H_W2;

    float* out = (float*)d_out;
    float* gate_out = nullptr;
    if ((size_t)out_size >= (size_t)NTOK * Dc + (size_t)NTOK * Ec)
        gate_out = out + (size_t)NTOK * Dc;

    // raise dynamic smem limits (host-side attribute sets; not stream ops)
    cudaFuncSetAttribute(hgemm<128,0>, cudaFuncAttributeMaxDynamicSharedMemorySize, SMEM_NT128);
    cudaFuncSetAttribute(hgemm<128,1>, cudaFuncAttributeMaxDynamicSharedMemorySize, SMEM_NT128);
    cudaFuncSetAttribute(hgemm<128,2>, cudaFuncAttributeMaxDynamicSharedMemorySize, SMEM_NT128);
    cudaFuncSetAttribute(hgemm<128,3>, cudaFuncAttributeMaxDynamicSharedMemorySize, SMEM_NT128);
    cudaFuncSetAttribute(hgemm<128,5>, cudaFuncAttributeMaxDynamicSharedMemorySize, SMEM_NT128);
    cudaFuncSetAttribute(hgemm<128,6>, cudaFuncAttributeMaxDynamicSharedMemorySize, SMEM_NT128);
    cudaFuncSetAttribute(hgemm<128,7>, cudaFuncAttributeMaxDynamicSharedMemorySize, SMEM_NT128);
    cudaFuncSetAttribute(hgemm<64,6>,  cudaFuncAttributeMaxDynamicSharedMemorySize, SMEM_NT64);

    const dim3 blk(256);
    const dim3 tblk(32, 8);

    // 0) conversions
    conv16<<<(NTOK * Dc / 4 + 255) / 256, 256>>>(hidden, hid16, NTOK * Dc / 4);
    tconv<<<dim3(Dc / 32, Dc / 32, 1), tblk>>>(wq, wqT, Dc, Dc);
    tconv<<<dim3(Dc / 32, Dc / 32, 1), tblk>>>(wk, wkT, Dc, Dc);
    tconv<<<dim3(Dc / 32, Dc / 32, 1), tblk>>>(wv, wvT, Dc, Dc);
    tconv<<<dim3(Dc / 32, Dc / 32, 1), tblk>>>(wo, woT, Dc, Dc);
    tconv<<<dim3(Fc / 32, Dc / 32, Ec), tblk>>>(w1, w1T, Dc, Fc);
    tconv<<<dim3(Dc / 32, Fc / 32, Ec), tblk>>>(w2, w2T, Fc, Dc);

    // 1) Q/K projections -> fp16; V projection -> vT (transposed scatter)
    {
        dim3 grid(Dc / 128, NTOK / 128, 1);
        hgemm<128,6><<<grid, blk, SMEM_NT128>>>(hid16, wqT, nullptr, q16, bq, nullptr,
            Dc, Dc, Dc, Dc, 0, 0.f, 1, 0,0,0,0,0,0,0);
        hgemm<128,6><<<grid, blk, SMEM_NT128>>>(hid16, wkT, nullptr, k16, bk, nullptr,
            Dc, Dc, Dc, Dc, 0, 0.f, 1, 0,0,0,0,0,0,0);
        hgemm<128,7><<<grid, blk, SMEM_NT128>>>(hid16, wvT, nullptr, vT16, bv, nullptr,
            Dc, Dc, Dc, Dc, 0, 0.f, 1, 0,0,0,0,0,0,0);
    }

    // 2) scores = QK^T/8 + mask (per b,h; K=64)
    {
        dim3 grid(Sc / 128, Sc / 128, Bc * Hc);
        hgemm<128,3><<<grid, blk, SMEM_NT128>>>(q16, k16, scores, nullptr, nullptr, mask,
            DHc, Dc, Dc, Sc, Sc, 0.125f, Hc,
            (long long)Sc * Dc, DHc,
            (long long)Sc * Dc, DHc,
            (long long)Hc * Sc * Sc, (long long)Sc * Sc,
            (long long)Sc * Sc);
    }

    // 3) softmax -> fp16 probs
    softmax2048<<<Bc * Hc * Sc, 256>>>(scores, pr16);

    // 4) ctx = probs @ V   (B operand = vT [DH,S] rows, N=64 per head)
    {
        dim3 grid(1, Sc / 128, Bc * Hc);
        hgemm<64,6><<<grid, blk, SMEM_NT64>>>(pr16, vT16, nullptr, ctx16, nullptr, nullptr,
            Sc, Sc, Sc, Dc, 0, 0.f, Hc,
            (long long)Hc * Sc * Sc, (long long)Sc * Sc,
            (long long)Hc * DHc * Sc, (long long)DHc * Sc,
            (long long)Sc * Dc, (long long)DHc, 0);
    }

    // 5) output projection -> fp32 attn
    {
        dim3 grid(Dc / 128, NTOK / 128, 1);
        hgemm<128,0><<<grid, blk, SMEM_NT128>>>(ctx16, woT, attn, nullptr, bo, nullptr,
            Dc, Dc, Dc, Dc, 0, 0.f, 1, 0,0,0,0,0,0,0);
    }

    // 6) inter = LN1(attn + hidden)  (fp32 + fp16)
    ln_residual<<<NTOK, 256>>>(attn, hidden, ln1_g, ln1_b, inter, int16_);

    // 7) gate
    gate_kernel<<<NTOK, 256>>>(inter, gate_w, gate_b, gate, gate_out);

    // 8) MoE
    for (int e = 0; e < Ec; e++) {
        dim3 gh(Fc / 128, NTOK / 128, 1);
        hgemm<128,1><<<gh, blk, SMEM_NT128>>>(int16_, w1T + (size_t)e * Dc * Fc,
            nullptr, h16, b1 + (size_t)e * Fc, nullptr,
            Dc, Dc, Dc, Fc, 0, 0.f, 1, 0,0,0,0,0,0,0);

        dim3 gy(Dc / 128, NTOK / 128, 1);
        if (e == 0)
            hgemm<128,2><<<gy, blk, SMEM_NT128>>>(h16, w2T + (size_t)e * Fc * Dc,
                moe, nullptr, b2 + (size_t)e * Dc, gate + e,
                Fc, Fc, Fc, Dc, Ec, 0.f, 1, 0,0,0,0,0,0,0);
        else
            hgemm<128,5><<<gy, blk, SMEM_NT128>>>(h16, w2T + (size_t)e * Fc * Dc,
                moe, nullptr, b2 + (size_t)e * Dc, gate + e,
                Fc, Fc, Fc, Dc, Ec, 0.f, 1, 0,0,0,0,0,0,0);
    }

    // 9) output = LN2(moe + inter)
    ln_residual<<<NTOK, 256>>>(moe, inter, ln2_g, ln2_b, out, nullptr);
}